// round 7
// baseline (speedup 1.0000x reference)
#include <cuda_runtime.h>
#include <cuda_bf16.h>
#include <cstdint>
#include <cstddef>

// Problem dims (fixed by the dataset)
#define DIN   4096
#define DOUT  4096
#define MTOT  16384            // B*S = 4*4096
#define LORA_R 16
#define LORA_SCALE 2.0f        // alpha/r = 32/16

// ---------------------------------------------------------------------------
// Scratch: pre-converted bf16 hi/lo splits (device globals; no allocation)
// ---------------------------------------------------------------------------
__device__ __nv_bfloat16 g_xhi[(size_t)MTOT * DIN];
__device__ __nv_bfloat16 g_xlo[(size_t)MTOT * DIN];
__device__ __nv_bfloat16 g_whi[(size_t)DOUT * DIN];
__device__ __nv_bfloat16 g_wlo[(size_t)DOUT * DIN];

// ---------------------------------------------------------------------------
// Baseline-PTX helpers (no 'a'-suffix features: mma.sync / ldmatrix / cp.async)
// ---------------------------------------------------------------------------
__device__ __forceinline__ uint32_t smem_to_u32(const void* smem_ptr) {
    uint32_t addr;
    asm("{ .reg .u64 tmp; cvta.to.shared.u64 tmp, %1; cvt.u32.u64 %0, tmp; }"
        : "=r"(addr) : "l"(smem_ptr));
    return addr;
}

__device__ __forceinline__ void cp_async16(uint32_t dst, const void* src) {
    asm volatile("cp.async.cg.shared.global [%0], [%1], 16;"
                 :: "r"(dst), "l"(src));
}
__device__ __forceinline__ void cp_commit() {
    asm volatile("cp.async.commit_group;" ::: "memory");
}
template <int N>
__device__ __forceinline__ void cp_wait_group() {
    asm volatile("cp.async.wait_group %0;" :: "n"(N) : "memory");
}

__device__ __forceinline__ void ldsm4(uint32_t* r, uint32_t addr) {
    asm volatile("ldmatrix.sync.aligned.m8n8.x4.shared.b16 {%0,%1,%2,%3}, [%4];"
                 : "=r"(r[0]), "=r"(r[1]), "=r"(r[2]), "=r"(r[3]) : "r"(addr));
}

// D(16x8) += A(16x16,row) * B(8x16 stored [n][k] i.e. col-major KxN), bf16->f32
__device__ __forceinline__ void mma_bf16(float* c, const uint32_t* a, const uint32_t* b) {
    asm volatile(
        "mma.sync.aligned.m16n8k16.row.col.f32.bf16.bf16.f32 "
        "{%0,%1,%2,%3}, {%4,%5,%6,%7}, {%8,%9}, {%0,%1,%2,%3};"
        : "+f"(c[0]), "+f"(c[1]), "+f"(c[2]), "+f"(c[3])
        : "r"(a[0]), "r"(a[1]), "r"(a[2]), "r"(a[3]), "r"(b[0]), "r"(b[1]));
}

// ---------------------------------------------------------------------------
// Pre-pass 1: split x (fp32) into bf16 hi/lo
// ---------------------------------------------------------------------------
__global__ void prep_x_kernel(const float4* __restrict__ x4) {
    size_t i = (size_t)blockIdx.x * 256 + threadIdx.x;   // 16,777,216 threads
    float4 v = x4[i];
    __nv_bfloat16 h0 = __float2bfloat16(v.x);
    __nv_bfloat16 h1 = __float2bfloat16(v.y);
    __nv_bfloat16 h2 = __float2bfloat16(v.z);
    __nv_bfloat16 h3 = __float2bfloat16(v.w);
    __nv_bfloat16 l0 = __float2bfloat16(v.x - __bfloat162float(h0));
    __nv_bfloat16 l1 = __float2bfloat16(v.y - __bfloat162float(h1));
    __nv_bfloat16 l2 = __float2bfloat16(v.z - __bfloat162float(h2));
    __nv_bfloat16 l3 = __float2bfloat16(v.w - __bfloat162float(h3));
    uint2 hp, lp;
    hp.x = ((uint32_t)__bfloat16_as_ushort(h1) << 16) | __bfloat16_as_ushort(h0);
    hp.y = ((uint32_t)__bfloat16_as_ushort(h3) << 16) | __bfloat16_as_ushort(h2);
    lp.x = ((uint32_t)__bfloat16_as_ushort(l1) << 16) | __bfloat16_as_ushort(l0);
    lp.y = ((uint32_t)__bfloat16_as_ushort(l3) << 16) | __bfloat16_as_ushort(l2);
    reinterpret_cast<uint2*>(g_xhi)[i] = hp;
    reinterpret_cast<uint2*>(g_xlo)[i] = lp;
}

// ---------------------------------------------------------------------------
// Pre-pass 2: W_eff[n,k] = W[n,k] + SCALE * sum_r A[k,r]*B[r,n], split hi/lo
// ---------------------------------------------------------------------------
__global__ void prep_w_kernel(const float* __restrict__ W,
                              const float* __restrict__ lA,
                              const float* __restrict__ lB) {
    int idx = blockIdx.x * 256 + threadIdx.x;            // 16,777,216 threads
    int n = idx >> 12;
    int k = idx & 4095;
    float acc = W[idx];                                  // W is [DOUT, DIN] row-major
    const float4* a4 = reinterpret_cast<const float4*>(lA + (size_t)k * LORA_R);
#pragma unroll
    for (int r4 = 0; r4 < 4; r4++) {
        float4 a = a4[r4];
        acc = fmaf(LORA_SCALE * a.x, __ldg(lB + (size_t)(r4 * 4 + 0) * DOUT + n), acc);
        acc = fmaf(LORA_SCALE * a.y, __ldg(lB + (size_t)(r4 * 4 + 1) * DOUT + n), acc);
        acc = fmaf(LORA_SCALE * a.z, __ldg(lB + (size_t)(r4 * 4 + 2) * DOUT + n), acc);
        acc = fmaf(LORA_SCALE * a.w, __ldg(lB + (size_t)(r4 * 4 + 3) * DOUT + n), acc);
    }
    __nv_bfloat16 h = __float2bfloat16(acc);
    g_whi[idx] = h;
    g_wlo[idx] = __float2bfloat16(acc - __bfloat162float(h));
}

// ---------------------------------------------------------------------------
// Main GEMM (Ampere-style, baseline PTX only):
//   CTA tile 128x128, BK=32, 4-stage cp.async pipeline,
//   8 warps as 2(M) x 4(N), warp tile 64x32,
//   3-term bf16 split: Ahi*Bhi + Ahi*Blo + Alo*Bhi, fp32 accumulators.
// SMEM tile rows are 80B-strided (64B data + 16B pad) -> conflict-free LDSM.
// ---------------------------------------------------------------------------
#define BK          32
#define ROW_STRIDE  80                       // 32 bf16 = 64B + 16B pad
#define TILE_BYTES  (128 * ROW_STRIDE)       // 10240
#define STAGE_BYTES (4 * TILE_BYTES)         // Ahi, Alo, Bhi, Blo = 40960
#define NSTAGE      4
#define SMEM_TOTAL  (NSTAGE * STAGE_BYTES)   // 163840
#define OFF_ALO     TILE_BYTES
#define OFF_BHI     (2 * TILE_BYTES)
#define OFF_BLO     (3 * TILE_BYTES)

__global__ void __launch_bounds__(256, 1)
lora_main_kernel(const float* __restrict__ bias, float* __restrict__ out)
{
    extern __shared__ char smem[];
    const uint32_t smem_base = smem_to_u32(smem);
    const int tid    = threadIdx.x;
    const int lane   = tid & 31;
    const int wid    = tid >> 5;
    const int warp_m = wid >> 2;             // 0..1 (64 rows each)
    const int warp_n = wid & 3;              // 0..3 (32 cols each)
    const int n0 = blockIdx.x * 128;         // N tile fastest -> W_eff L2-resident
    const int m0 = blockIdx.y * 128;

    // ---- cp.async slots: 2 x 16B chunks per tile per thread -------------
    const int row0 = tid >> 2;               // 0..63
    const int c0   = tid & 3;                // 16B chunk within 64B row
    const uint32_t so0 = (uint32_t)(row0 * ROW_STRIDE + c0 * 16);
    const uint32_t so1 = so0 + 64 * ROW_STRIDE;
    // global byte pointers for chunk (row, c) at k-chunk 0
    const char* pA0h = (const char*)g_xhi + ((size_t)(m0 + row0) * DIN + c0 * 8) * 2;
    const char* pA0l = (const char*)g_xlo + ((size_t)(m0 + row0) * DIN + c0 * 8) * 2;
    const char* pB0h = (const char*)g_whi + ((size_t)(n0 + row0) * DIN + c0 * 8) * 2;
    const char* pB0l = (const char*)g_wlo + ((size_t)(n0 + row0) * DIN + c0 * 8) * 2;
    const size_t rstep = (size_t)64 * DIN * 2;   // +64 rows

    const int NCH = DIN / BK;                // 128 k-chunks

    auto issue_stage = [&](int s) {
        if (s < NCH) {
            const uint32_t sb = smem_base + (uint32_t)(s & (NSTAGE - 1)) * STAGE_BYTES;
            const size_t g = (size_t)s * (BK * 2);   // 64 bytes per k-chunk
            cp_async16(sb + so0,            pA0h + g);
            cp_async16(sb + so1,            pA0h + g + rstep);
            cp_async16(sb + OFF_ALO + so0,  pA0l + g);
            cp_async16(sb + OFF_ALO + so1,  pA0l + g + rstep);
            cp_async16(sb + OFF_BHI + so0,  pB0h + g);
            cp_async16(sb + OFF_BHI + so1,  pB0h + g + rstep);
            cp_async16(sb + OFF_BLO + so0,  pB0l + g);
            cp_async16(sb + OFF_BLO + so1,  pB0l + g + rstep);
        }
        cp_commit();                         // commit even when empty (group count)
    };

    // ---- ldmatrix address bases (per thread) ----------------------------
    // A (fragment order: row-blocks first, then k-halves):
    //   lanes 0-7  -> rows 0-7  @ k0-7   (a0)
    //   lanes 8-15 -> rows 8-15 @ k0-7   (a1)
    //   lanes 16-23-> rows 0-7  @ k8-15  (a2)
    //   lanes 24-31-> rows 8-15 @ k8-15  (a3)
    const uint32_t a_off = (uint32_t)((warp_m * 64 + (lane & 15)) * ROW_STRIDE + (lane >> 4) * 16);
    // B (fragment order: k-halves first within an n-block — {b0,b1} must be
    //  {B[n,k0-7], B[n,k8-15]} of the SAME n-block):
    //   lanes 0-7  -> n-rows 0-7  @ k0-7   (reg0 = b0 of n0-7)
    //   lanes 8-15 -> n-rows 0-7  @ k8-15  (reg1 = b1 of n0-7)
    //   lanes 16-23-> n-rows 8-15 @ k0-7   (reg2 = b0 of n8-15)
    //   lanes 24-31-> n-rows 8-15 @ k8-15  (reg3 = b1 of n8-15)
    const int b_row  = (lane & 7) + ((lane >> 4) << 3);
    const int b_koff = ((lane >> 3) & 1) * 16;
    const uint32_t b_off = (uint32_t)((warp_n * 32 + b_row) * ROW_STRIDE + b_koff);

    float acc[4][4][4];
#pragma unroll
    for (int i = 0; i < 4; i++)
#pragma unroll
        for (int j = 0; j < 4; j++)
#pragma unroll
            for (int e = 0; e < 4; e++) acc[i][j][e] = 0.0f;

    // Prologue: prefetch 3 stages
    issue_stage(0); issue_stage(1); issue_stage(2);

    for (int ic = 0; ic < NCH; ++ic) {
        cp_wait_group<2>();                  // stage ic landed
        __syncthreads();                     // visible to all warps; buf (ic-1)%4 free
        issue_stage(ic + 3);

        const uint32_t sb = smem_base + (uint32_t)(ic & (NSTAGE - 1)) * STAGE_BYTES;
        const uint32_t aA = sb + a_off;
        const uint32_t aB = sb + OFF_BHI + b_off;
#pragma unroll
        for (int ks = 0; ks < 2; ks++) {
            uint32_t Ahi[4][4], Alo[4][4], Bhi[2][4], Blo[2][4];
#pragma unroll
            for (int mf = 0; mf < 4; mf++) {
                ldsm4(Ahi[mf], aA + mf * (16 * ROW_STRIDE) + ks * 32);
                ldsm4(Alo[mf], aA + OFF_ALO + mf * (16 * ROW_STRIDE) + ks * 32);
            }
#pragma unroll
            for (int nb = 0; nb < 2; nb++) {
                ldsm4(Bhi[nb], aB + nb * (16 * ROW_STRIDE) + ks * 32);
                ldsm4(Blo[nb], aB + TILE_BYTES + nb * (16 * ROW_STRIDE) + ks * 32);
            }
#pragma unroll
            for (int mf = 0; mf < 4; mf++)
#pragma unroll
                for (int nf = 0; nf < 4; nf++) {
                    mma_bf16(acc[mf][nf], Ahi[mf], &Bhi[nf >> 1][(nf & 1) * 2]);
                    mma_bf16(acc[mf][nf], Ahi[mf], &Blo[nf >> 1][(nf & 1) * 2]);
                    mma_bf16(acc[mf][nf], Alo[mf], &Bhi[nf >> 1][(nf & 1) * 2]);
                }
        }
    }

    // ---- epilogue: D += bias, write fp32 --------------------------------
    const int row_base = m0 + warp_m * 64 + (lane >> 2);
    const int col_base = n0 + warp_n * 32 + (lane & 3) * 2;
    float bx[4][2];
#pragma unroll
    for (int nf = 0; nf < 4; nf++) {
        bx[nf][0] = bias[col_base + nf * 8];
        bx[nf][1] = bias[col_base + nf * 8 + 1];
    }
#pragma unroll
    for (int mf = 0; mf < 4; mf++) {
        float* p0 = out + (size_t)(row_base + mf * 16) * DOUT + col_base;
        float* p1 = p0 + 8 * DOUT;
#pragma unroll
        for (int nf = 0; nf < 4; nf++) {
            float2 v0, v1;
            v0.x = acc[mf][nf][0] + bx[nf][0];
            v0.y = acc[mf][nf][1] + bx[nf][1];
            v1.x = acc[mf][nf][2] + bx[nf][0];
            v1.y = acc[mf][nf][3] + bx[nf][1];
            *reinterpret_cast<float2*>(p0 + nf * 8) = v0;
            *reinterpret_cast<float2*>(p1 + nf * 8) = v1;
        }
    }
}

// ---------------------------------------------------------------------------
// kernel_launch: prep_x, prep_w, then the GEMM. Graph-capturable; no allocs.
// ---------------------------------------------------------------------------
extern "C" void kernel_launch(void* const* d_in, const int* in_sizes, int n_in,
                              void* d_out, int out_size) {
    const float* x  = (const float*)d_in[0];   // [4,4096,4096]
    const float* W  = (const float*)d_in[1];   // [4096,4096]
    const float* b  = (const float*)d_in[2];   // [4096]
    const float* lA = (const float*)d_in[3];   // [4096,16]
    const float* lB = (const float*)d_in[4];   // [16,4096]
    float* out = (float*)d_out;

    prep_x_kernel<<<(MTOT * (size_t)DIN) / 4 / 256, 256>>>(
        reinterpret_cast<const float4*>(x));
    prep_w_kernel<<<(DOUT * (size_t)DIN) / 256, 256>>>(W, lA, lB);

    cudaFuncSetAttribute(lora_main_kernel,
                         cudaFuncAttributeMaxDynamicSharedMemorySize, SMEM_TOTAL);
    dim3 grid(DOUT / 128, MTOT / 128);   // (32, 128): N fastest for L2 reuse of W
    lora_main_kernel<<<grid, 256, SMEM_TOTAL>>>(b, out);
}

// round 8
// speedup vs baseline: 1.1113x; 1.1113x over previous
#include <cuda_runtime.h>
#include <cuda_bf16.h>
#include <cstdint>
#include <cstddef>

// Problem dims (fixed by the dataset)
#define DIN   4096
#define DOUT  4096
#define MTOT  16384            // B*S = 4*4096
#define LORA_R 16
#define LORA_SCALE 2.0f        // alpha/r = 32/16

// ---------------------------------------------------------------------------
// Scratch: pre-converted bf16 hi/lo splits (device globals; no allocation)
// ---------------------------------------------------------------------------
__device__ __nv_bfloat16 g_xhi[(size_t)MTOT * DIN];
__device__ __nv_bfloat16 g_xlo[(size_t)MTOT * DIN];
__device__ __nv_bfloat16 g_whi[(size_t)DOUT * DIN];
__device__ __nv_bfloat16 g_wlo[(size_t)DOUT * DIN];

// ---------------------------------------------------------------------------
// Baseline-PTX helpers (no 'a'-suffix features: mma.sync / ldmatrix / cp.async)
// ---------------------------------------------------------------------------
__device__ __forceinline__ uint32_t smem_to_u32(const void* smem_ptr) {
    uint32_t addr;
    asm("{ .reg .u64 tmp; cvta.to.shared.u64 tmp, %1; cvt.u32.u64 %0, tmp; }"
        : "=r"(addr) : "l"(smem_ptr));
    return addr;
}

__device__ __forceinline__ void cp_async16(uint32_t dst, const void* src) {
    asm volatile("cp.async.cg.shared.global [%0], [%1], 16;"
                 :: "r"(dst), "l"(src));
}
__device__ __forceinline__ void cp_commit() {
    asm volatile("cp.async.commit_group;" ::: "memory");
}
template <int N>
__device__ __forceinline__ void cp_wait_group() {
    asm volatile("cp.async.wait_group %0;" :: "n"(N) : "memory");
}

__device__ __forceinline__ void ldsm4(uint32_t* r, uint32_t addr) {
    asm volatile("ldmatrix.sync.aligned.m8n8.x4.shared.b16 {%0,%1,%2,%3}, [%4];"
                 : "=r"(r[0]), "=r"(r[1]), "=r"(r[2]), "=r"(r[3]) : "r"(addr));
}

// D(16x8) += A(16x16,row) * B(8x16 stored [n][k] i.e. col-major KxN), bf16->f32
__device__ __forceinline__ void mma_bf16(float* c, const uint32_t* a, const uint32_t* b) {
    asm volatile(
        "mma.sync.aligned.m16n8k16.row.col.f32.bf16.bf16.f32 "
        "{%0,%1,%2,%3}, {%4,%5,%6,%7}, {%8,%9}, {%0,%1,%2,%3};"
        : "+f"(c[0]), "+f"(c[1]), "+f"(c[2]), "+f"(c[3])
        : "r"(a[0]), "r"(a[1]), "r"(a[2]), "r"(a[3]), "r"(b[0]), "r"(b[1]));
}

// ---------------------------------------------------------------------------
// Pre-pass 1: split x (fp32) into bf16 hi/lo
// ---------------------------------------------------------------------------
__global__ void prep_x_kernel(const float4* __restrict__ x4) {
    size_t i = (size_t)blockIdx.x * 256 + threadIdx.x;   // 16,777,216 threads
    float4 v = x4[i];
    __nv_bfloat16 h0 = __float2bfloat16(v.x);
    __nv_bfloat16 h1 = __float2bfloat16(v.y);
    __nv_bfloat16 h2 = __float2bfloat16(v.z);
    __nv_bfloat16 h3 = __float2bfloat16(v.w);
    __nv_bfloat16 l0 = __float2bfloat16(v.x - __bfloat162float(h0));
    __nv_bfloat16 l1 = __float2bfloat16(v.y - __bfloat162float(h1));
    __nv_bfloat16 l2 = __float2bfloat16(v.z - __bfloat162float(h2));
    __nv_bfloat16 l3 = __float2bfloat16(v.w - __bfloat162float(h3));
    uint2 hp, lp;
    hp.x = ((uint32_t)__bfloat16_as_ushort(h1) << 16) | __bfloat16_as_ushort(h0);
    hp.y = ((uint32_t)__bfloat16_as_ushort(h3) << 16) | __bfloat16_as_ushort(h2);
    lp.x = ((uint32_t)__bfloat16_as_ushort(l1) << 16) | __bfloat16_as_ushort(l0);
    lp.y = ((uint32_t)__bfloat16_as_ushort(l3) << 16) | __bfloat16_as_ushort(l2);
    reinterpret_cast<uint2*>(g_xhi)[i] = hp;
    reinterpret_cast<uint2*>(g_xlo)[i] = lp;
}

// ---------------------------------------------------------------------------
// Pre-pass 2: W_eff[n,k] = W[n,k] + SCALE * sum_r A[k,r]*B[r,n], split hi/lo
// ---------------------------------------------------------------------------
__global__ void prep_w_kernel(const float* __restrict__ W,
                              const float* __restrict__ lA,
                              const float* __restrict__ lB) {
    int idx = blockIdx.x * 256 + threadIdx.x;            // 16,777,216 threads
    int n = idx >> 12;
    int k = idx & 4095;
    float acc = W[idx];                                  // W is [DOUT, DIN] row-major
    const float4* a4 = reinterpret_cast<const float4*>(lA + (size_t)k * LORA_R);
#pragma unroll
    for (int r4 = 0; r4 < 4; r4++) {
        float4 a = a4[r4];
        acc = fmaf(LORA_SCALE * a.x, __ldg(lB + (size_t)(r4 * 4 + 0) * DOUT + n), acc);
        acc = fmaf(LORA_SCALE * a.y, __ldg(lB + (size_t)(r4 * 4 + 1) * DOUT + n), acc);
        acc = fmaf(LORA_SCALE * a.z, __ldg(lB + (size_t)(r4 * 4 + 2) * DOUT + n), acc);
        acc = fmaf(LORA_SCALE * a.w, __ldg(lB + (size_t)(r4 * 4 + 3) * DOUT + n), acc);
    }
    __nv_bfloat16 h = __float2bfloat16(acc);
    g_whi[idx] = h;
    g_wlo[idx] = __float2bfloat16(acc - __bfloat162float(h));
}

// ---------------------------------------------------------------------------
// Main GEMM (Ampere-style, baseline PTX only):
//   CTA tile 128x128, BK=32, 4-stage cp.async pipeline,
//   512 threads / 16 warps as 4(M) x 4(N), warp tile 32x32,
//   3-term bf16 split: Ahi*Bhi + Ahi*Blo + Alo*Bhi, fp32 accumulators.
// SMEM tile rows are 80B-strided (64B data + 16B pad) -> conflict-free LDSM
// (row offsets mod 128B = {0,80,32,112,64,16,96,48}: all 8 slots distinct).
// ---------------------------------------------------------------------------
#define BK          32
#define ROW_STRIDE  80                       // 32 bf16 = 64B + 16B pad
#define TILE_BYTES  (128 * ROW_STRIDE)       // 10240
#define STAGE_BYTES (4 * TILE_BYTES)         // Ahi, Alo, Bhi, Blo = 40960
#define NSTAGE      4
#define SMEM_TOTAL  (NSTAGE * STAGE_BYTES)   // 163840
#define OFF_ALO     TILE_BYTES
#define OFF_BHI     (2 * TILE_BYTES)
#define OFF_BLO     (3 * TILE_BYTES)

__global__ void __launch_bounds__(512, 1)
lora_main_kernel(const float* __restrict__ bias, float* __restrict__ out)
{
    extern __shared__ char smem[];
    const uint32_t smem_base = smem_to_u32(smem);
    const int tid    = threadIdx.x;
    const int lane   = tid & 31;
    const int wid    = tid >> 5;
    const int warp_m = wid >> 2;             // 0..3 (32 rows each)
    const int warp_n = wid & 3;              // 0..3 (32 cols each)
    const int n0 = blockIdx.x * 128;         // N tile fastest -> W_eff L2-resident
    const int m0 = blockIdx.y * 128;

    // ---- cp.async slots: 1 x 16B chunk per tile per thread ---------------
    const int row0 = tid >> 2;               // 0..127
    const int c0   = tid & 3;                // 16B chunk within 64B row
    const uint32_t so0 = (uint32_t)(row0 * ROW_STRIDE + c0 * 16);
    // global byte pointers for chunk (row, c) at k-chunk 0
    const char* pA0h = (const char*)g_xhi + ((size_t)(m0 + row0) * DIN + c0 * 8) * 2;
    const char* pA0l = (const char*)g_xlo + ((size_t)(m0 + row0) * DIN + c0 * 8) * 2;
    const char* pB0h = (const char*)g_whi + ((size_t)(n0 + row0) * DIN + c0 * 8) * 2;
    const char* pB0l = (const char*)g_wlo + ((size_t)(n0 + row0) * DIN + c0 * 8) * 2;

    const int NCH = DIN / BK;                // 128 k-chunks

    auto issue_stage = [&](int s) {
        if (s < NCH) {
            const uint32_t sb = smem_base + (uint32_t)(s & (NSTAGE - 1)) * STAGE_BYTES;
            const size_t g = (size_t)s * (BK * 2);   // 64 bytes per k-chunk
            cp_async16(sb + so0,            pA0h + g);
            cp_async16(sb + OFF_ALO + so0,  pA0l + g);
            cp_async16(sb + OFF_BHI + so0,  pB0h + g);
            cp_async16(sb + OFF_BLO + so0,  pB0l + g);
        }
        cp_commit();                         // commit even when empty (group count)
    };

    // ---- ldmatrix address bases (per thread) ----------------------------
    // A (fragment order: row-blocks first, then k-halves):
    //   lanes 0-7  -> rows 0-7  @ k0-7   (a0)
    //   lanes 8-15 -> rows 8-15 @ k0-7   (a1)
    //   lanes 16-23-> rows 0-7  @ k8-15  (a2)
    //   lanes 24-31-> rows 8-15 @ k8-15  (a3)
    const uint32_t a_off = (uint32_t)((warp_m * 32 + (lane & 15)) * ROW_STRIDE + (lane >> 4) * 16);
    // B (fragment order: k-halves first within an n-block — {b0,b1} must be
    //  {B[n,k0-7], B[n,k8-15]} of the SAME n-block):
    //   lanes 0-7  -> n-rows 0-7  @ k0-7   (reg0 = b0 of n0-7)
    //   lanes 8-15 -> n-rows 0-7  @ k8-15  (reg1 = b1 of n0-7)
    //   lanes 16-23-> n-rows 8-15 @ k0-7   (reg2 = b0 of n8-15)
    //   lanes 24-31-> n-rows 8-15 @ k8-15  (reg3 = b1 of n8-15)
    const int b_row  = (lane & 7) + ((lane >> 4) << 3);
    const int b_koff = ((lane >> 3) & 1) * 16;
    const uint32_t b_off = (uint32_t)((warp_n * 32 + b_row) * ROW_STRIDE + b_koff);

    float acc[2][4][4];
#pragma unroll
    for (int i = 0; i < 2; i++)
#pragma unroll
        for (int j = 0; j < 4; j++)
#pragma unroll
            for (int e = 0; e < 4; e++) acc[i][j][e] = 0.0f;

    // Prologue: prefetch 3 stages
    issue_stage(0); issue_stage(1); issue_stage(2);

    for (int ic = 0; ic < NCH; ++ic) {
        cp_wait_group<2>();                  // stage ic landed
        __syncthreads();                     // visible to all warps; buf (ic-1)%4 free
        issue_stage(ic + 3);

        const uint32_t sb = smem_base + (uint32_t)(ic & (NSTAGE - 1)) * STAGE_BYTES;
        const uint32_t aA = sb + a_off;
        const uint32_t aB = sb + OFF_BHI + b_off;
#pragma unroll
        for (int ks = 0; ks < 2; ks++) {
            uint32_t Ahi[2][4], Alo[2][4], Bhi[2][4], Blo[2][4];
#pragma unroll
            for (int mf = 0; mf < 2; mf++) {
                ldsm4(Ahi[mf], aA + mf * (16 * ROW_STRIDE) + ks * 32);
                ldsm4(Alo[mf], aA + OFF_ALO + mf * (16 * ROW_STRIDE) + ks * 32);
            }
#pragma unroll
            for (int nb = 0; nb < 2; nb++) {
                ldsm4(Bhi[nb], aB + nb * (16 * ROW_STRIDE) + ks * 32);
                ldsm4(Blo[nb], aB + TILE_BYTES + nb * (16 * ROW_STRIDE) + ks * 32);
            }
#pragma unroll
            for (int mf = 0; mf < 2; mf++)
#pragma unroll
                for (int nf = 0; nf < 4; nf++) {
                    mma_bf16(acc[mf][nf], Ahi[mf], &Bhi[nf >> 1][(nf & 1) * 2]);
                    mma_bf16(acc[mf][nf], Ahi[mf], &Blo[nf >> 1][(nf & 1) * 2]);
                    mma_bf16(acc[mf][nf], Alo[mf], &Bhi[nf >> 1][(nf & 1) * 2]);
                }
        }
    }

    // ---- epilogue: D += bias, write fp32 --------------------------------
    const int row_base = m0 + warp_m * 32 + (lane >> 2);
    const int col_base = n0 + warp_n * 32 + (lane & 3) * 2;
    float bx[4][2];
#pragma unroll
    for (int nf = 0; nf < 4; nf++) {
        bx[nf][0] = bias[col_base + nf * 8];
        bx[nf][1] = bias[col_base + nf * 8 + 1];
    }
#pragma unroll
    for (int mf = 0; mf < 2; mf++) {
        float* p0 = out + (size_t)(row_base + mf * 16) * DOUT + col_base;
        float* p1 = p0 + 8 * DOUT;
#pragma unroll
        for (int nf = 0; nf < 4; nf++) {
            float2 v0, v1;
            v0.x = acc[mf][nf][0] + bx[nf][0];
            v0.y = acc[mf][nf][1] + bx[nf][1];
            v1.x = acc[mf][nf][2] + bx[nf][0];
            v1.y = acc[mf][nf][3] + bx[nf][1];
            *reinterpret_cast<float2*>(p0 + nf * 8) = v0;
            *reinterpret_cast<float2*>(p1 + nf * 8) = v1;
        }
    }
}

// ---------------------------------------------------------------------------
// kernel_launch: prep_x, prep_w, then the GEMM. Graph-capturable; no allocs.
// ---------------------------------------------------------------------------
extern "C" void kernel_launch(void* const* d_in, const int* in_sizes, int n_in,
                              void* d_out, int out_size) {
    const float* x  = (const float*)d_in[0];   // [4,4096,4096]
    const float* W  = (const float*)d_in[1];   // [4096,4096]
    const float* b  = (const float*)d_in[2];   // [4096]
    const float* lA = (const float*)d_in[3];   // [4096,16]
    const float* lB = (const float*)d_in[4];   // [16,4096]
    float* out = (float*)d_out;

    prep_x_kernel<<<(MTOT * (size_t)DIN) / 4 / 256, 256>>>(
        reinterpret_cast<const float4*>(x));
    prep_w_kernel<<<(DOUT * (size_t)DIN) / 256, 256>>>(W, lA, lB);

    cudaFuncSetAttribute(lora_main_kernel,
                         cudaFuncAttributeMaxDynamicSharedMemorySize, SMEM_TOTAL);
    dim3 grid(DOUT / 128, MTOT / 128);   // (32, 128): N fastest for L2 reuse of W
    lora_main_kernel<<<grid, 512, SMEM_TOTAL>>>(b, out);
}

// round 9
// speedup vs baseline: 1.1154x; 1.0037x over previous
#include <cuda_runtime.h>
#include <cuda_bf16.h>
#include <cstdint>
#include <cstddef>

// Problem dims (fixed by the dataset)
#define DIN   4096
#define DOUT  4096
#define MTOT  16384            // B*S = 4*4096
#define LORA_R 16
#define LORA_SCALE 2.0f        // alpha/r = 32/16

// ---------------------------------------------------------------------------
// Scratch: pre-converted bf16 hi/lo splits (device globals; no allocation)
// ---------------------------------------------------------------------------
__device__ __nv_bfloat16 g_xhi[(size_t)MTOT * DIN];
__device__ __nv_bfloat16 g_xlo[(size_t)MTOT * DIN];
__device__ __nv_bfloat16 g_whi[(size_t)DOUT * DIN];
__device__ __nv_bfloat16 g_wlo[(size_t)DOUT * DIN];

// ---------------------------------------------------------------------------
// Baseline-PTX helpers (no 'a'-suffix features: mma.sync / ldmatrix / cp.async)
// ---------------------------------------------------------------------------
__device__ __forceinline__ uint32_t smem_to_u32(const void* smem_ptr) {
    uint32_t addr;
    asm("{ .reg .u64 tmp; cvta.to.shared.u64 tmp, %1; cvt.u32.u64 %0, tmp; }"
        : "=r"(addr) : "l"(smem_ptr));
    return addr;
}

__device__ __forceinline__ void cp_async16(uint32_t dst, const void* src) {
    asm volatile("cp.async.cg.shared.global [%0], [%1], 16;"
                 :: "r"(dst), "l"(src));
}
__device__ __forceinline__ void cp_commit() {
    asm volatile("cp.async.commit_group;" ::: "memory");
}
template <int N>
__device__ __forceinline__ void cp_wait_group() {
    asm volatile("cp.async.wait_group %0;" :: "n"(N) : "memory");
}

__device__ __forceinline__ void ldsm4(uint32_t* r, uint32_t addr) {
    asm volatile("ldmatrix.sync.aligned.m8n8.x4.shared.b16 {%0,%1,%2,%3}, [%4];"
                 : "=r"(r[0]), "=r"(r[1]), "=r"(r[2]), "=r"(r[3]) : "r"(addr));
}

// D(16x8) += A(16x16,row) * B(8x16 stored [n][k] i.e. col-major KxN), bf16->f32
__device__ __forceinline__ void mma_bf16(float* c, const uint32_t* a, const uint32_t* b) {
    asm volatile(
        "mma.sync.aligned.m16n8k16.row.col.f32.bf16.bf16.f32 "
        "{%0,%1,%2,%3}, {%4,%5,%6,%7}, {%8,%9}, {%0,%1,%2,%3};"
        : "+f"(c[0]), "+f"(c[1]), "+f"(c[2]), "+f"(c[3])
        : "r"(a[0]), "r"(a[1]), "r"(a[2]), "r"(a[3]), "r"(b[0]), "r"(b[1]));
}

// ---------------------------------------------------------------------------
// Pre-pass 1: split x (fp32) into bf16 hi/lo
// ---------------------------------------------------------------------------
__global__ void prep_x_kernel(const float4* __restrict__ x4) {
    size_t i = (size_t)blockIdx.x * 256 + threadIdx.x;   // 16,777,216 threads
    float4 v = x4[i];
    __nv_bfloat16 h0 = __float2bfloat16(v.x);
    __nv_bfloat16 h1 = __float2bfloat16(v.y);
    __nv_bfloat16 h2 = __float2bfloat16(v.z);
    __nv_bfloat16 h3 = __float2bfloat16(v.w);
    __nv_bfloat16 l0 = __float2bfloat16(v.x - __bfloat162float(h0));
    __nv_bfloat16 l1 = __float2bfloat16(v.y - __bfloat162float(h1));
    __nv_bfloat16 l2 = __float2bfloat16(v.z - __bfloat162float(h2));
    __nv_bfloat16 l3 = __float2bfloat16(v.w - __bfloat162float(h3));
    uint2 hp, lp;
    hp.x = ((uint32_t)__bfloat16_as_ushort(h1) << 16) | __bfloat16_as_ushort(h0);
    hp.y = ((uint32_t)__bfloat16_as_ushort(h3) << 16) | __bfloat16_as_ushort(h2);
    lp.x = ((uint32_t)__bfloat16_as_ushort(l1) << 16) | __bfloat16_as_ushort(l0);
    lp.y = ((uint32_t)__bfloat16_as_ushort(l3) << 16) | __bfloat16_as_ushort(l2);
    reinterpret_cast<uint2*>(g_xhi)[i] = hp;
    reinterpret_cast<uint2*>(g_xlo)[i] = lp;
}

// ---------------------------------------------------------------------------
// Pre-pass 2: W_eff[n,k] = W[n,k] + SCALE * sum_r A[k,r]*B[r,n], split hi/lo
// ---------------------------------------------------------------------------
__global__ void prep_w_kernel(const float* __restrict__ W,
                              const float* __restrict__ lA,
                              const float* __restrict__ lB) {
    int idx = blockIdx.x * 256 + threadIdx.x;            // 16,777,216 threads
    int n = idx >> 12;
    int k = idx & 4095;
    float acc = W[idx];                                  // W is [DOUT, DIN] row-major
    const float4* a4 = reinterpret_cast<const float4*>(lA + (size_t)k * LORA_R);
#pragma unroll
    for (int r4 = 0; r4 < 4; r4++) {
        float4 a = a4[r4];
        acc = fmaf(LORA_SCALE * a.x, __ldg(lB + (size_t)(r4 * 4 + 0) * DOUT + n), acc);
        acc = fmaf(LORA_SCALE * a.y, __ldg(lB + (size_t)(r4 * 4 + 1) * DOUT + n), acc);
        acc = fmaf(LORA_SCALE * a.z, __ldg(lB + (size_t)(r4 * 4 + 2) * DOUT + n), acc);
        acc = fmaf(LORA_SCALE * a.w, __ldg(lB + (size_t)(r4 * 4 + 3) * DOUT + n), acc);
    }
    __nv_bfloat16 h = __float2bfloat16(acc);
    g_whi[idx] = h;
    g_wlo[idx] = __float2bfloat16(acc - __bfloat162float(h));
}

// ---------------------------------------------------------------------------
// Main GEMM (Ampere-style, baseline PTX only):
//   CTA tile 256(M) x 128(N), BK=32, 3-stage cp.async ring,
//   512 threads / 16 warps as 4(M) x 4(N), warp tile 64x32,
//   3-term bf16 split: Ahi*Bhi + Ahi*Blo + Alo*Bhi, fp32 accumulators.
// SMEM tile rows are 80B-strided (64B data + 16B pad) -> conflict-free LDSM
// (row offsets mod 128B = {0,80,32,112,64,16,96,48}: all 8 slots distinct).
// ---------------------------------------------------------------------------
#define BM          256
#define BN          128
#define BK          32
#define ROW_STRIDE  80                         // 32 bf16 = 64B + 16B pad
#define A_TILE_BYTES (BM * ROW_STRIDE)         // 20480
#define B_TILE_BYTES (BN * ROW_STRIDE)         // 10240
#define OFF_ALO     A_TILE_BYTES               // 20480
#define OFF_BHI     (2 * A_TILE_BYTES)         // 40960
#define OFF_BLO     (2 * A_TILE_BYTES + B_TILE_BYTES)  // 51200
#define STAGE_BYTES (2 * A_TILE_BYTES + 2 * B_TILE_BYTES)  // 61440
#define NSTAGE      3
#define SMEM_TOTAL  (NSTAGE * STAGE_BYTES)     // 184320

__global__ void __launch_bounds__(512, 1)
lora_main_kernel(const float* __restrict__ bias, float* __restrict__ out)
{
    extern __shared__ char smem[];
    const uint32_t smem_base = smem_to_u32(smem);
    const int tid    = threadIdx.x;
    const int lane   = tid & 31;
    const int wid    = tid >> 5;
    const int warp_m = wid >> 2;             // 0..3 (64 rows each)
    const int warp_n = wid & 3;              // 0..3 (32 cols each)
    const int n0 = blockIdx.x * BN;          // N tile fastest -> W_eff L2-resident
    const int m0 = blockIdx.y * BM;

    // ---- cp.async slots ---------------------------------------------------
    // A tiles: 256 rows x 4 chunks = 1024 chunks -> 2 per thread
    // B tiles: 128 rows x 4 chunks =  512 chunks -> 1 per thread
    const int rowA0 = tid >> 2;              // 0..127
    const int cA    = tid & 3;
    const uint32_t soA0 = (uint32_t)(rowA0 * ROW_STRIDE + cA * 16);
    const uint32_t soA1 = soA0 + 128 * ROW_STRIDE;
    const uint32_t soB  = soA0;              // same mapping, 128 rows
    const char* pAh0 = (const char*)g_xhi + ((size_t)(m0 + rowA0) * DIN + cA * 8) * 2;
    const char* pAl0 = (const char*)g_xlo + ((size_t)(m0 + rowA0) * DIN + cA * 8) * 2;
    const size_t rstep = (size_t)128 * DIN * 2;   // +128 rows
    const char* pBh  = (const char*)g_whi + ((size_t)(n0 + rowA0) * DIN + cA * 8) * 2;
    const char* pBl  = (const char*)g_wlo + ((size_t)(n0 + rowA0) * DIN + cA * 8) * 2;

    const int NCH = DIN / BK;                // 128 k-chunks

    auto issue_stage = [&](int s) {
        if (s < NCH) {
            const uint32_t sb = smem_base + (uint32_t)(s % NSTAGE) * STAGE_BYTES;
            const size_t g = (size_t)s * (BK * 2);   // 64 bytes per k-chunk
            cp_async16(sb + soA0,           pAh0 + g);
            cp_async16(sb + soA1,           pAh0 + g + rstep);
            cp_async16(sb + OFF_ALO + soA0, pAl0 + g);
            cp_async16(sb + OFF_ALO + soA1, pAl0 + g + rstep);
            cp_async16(sb + OFF_BHI + soB,  pBh + g);
            cp_async16(sb + OFF_BLO + soB,  pBl + g);
        }
        cp_commit();                         // commit even when empty (group count)
    };

    // ---- ldmatrix address bases (per thread) ----------------------------
    // A (fragment order: row-blocks first, then k-halves):
    //   lanes 0-7->rows0-7@k0-7 | 8-15->rows8-15@k0-7 | 16-23->rows0-7@k8-15 | 24-31->rows8-15@k8-15
    const uint32_t a_off = (uint32_t)((warp_m * 64 + (lane & 15)) * ROW_STRIDE + (lane >> 4) * 16);
    // B (fragment order: k-halves first within an n-block — {b0,b1} =
    //  {B[n,k0-7], B[n,k8-15]} of the SAME n-block):
    const int b_row  = (lane & 7) + ((lane >> 4) << 3);
    const int b_koff = ((lane >> 3) & 1) * 16;
    const uint32_t b_off = (uint32_t)((warp_n * 32 + b_row) * ROW_STRIDE + b_koff);

    float acc[4][4][4];
#pragma unroll
    for (int i = 0; i < 4; i++)
#pragma unroll
        for (int j = 0; j < 4; j++)
#pragma unroll
            for (int e = 0; e < 4; e++) acc[i][j][e] = 0.0f;

    // Prologue: prefetch 2 stages (3-stage ring, 2 in flight)
    issue_stage(0); issue_stage(1);

    for (int ic = 0; ic < NCH; ++ic) {
        cp_wait_group<1>();                  // stage ic landed (ic+1 may be in flight)
        __syncthreads();                     // all warps done with buf (ic-1)%3
        issue_stage(ic + 2);                 // refill the freed buffer

        const uint32_t sb = smem_base + (uint32_t)(ic % NSTAGE) * STAGE_BYTES;
        const uint32_t aA = sb + a_off;
        const uint32_t aB = sb + OFF_BHI + b_off;
#pragma unroll
        for (int ks = 0; ks < 2; ks++) {
            uint32_t Bhi[2][4], Blo[2][4];
#pragma unroll
            for (int nb = 0; nb < 2; nb++) {
                ldsm4(Bhi[nb], aB + nb * (16 * ROW_STRIDE) + ks * 32);
                ldsm4(Blo[nb], aB + B_TILE_BYTES + nb * (16 * ROW_STRIDE) + ks * 32);
            }
#pragma unroll
            for (int mf = 0; mf < 4; mf++) {
                uint32_t Ahi[4], Alo[4];
                ldsm4(Ahi, aA + mf * (16 * ROW_STRIDE) + ks * 32);
                ldsm4(Alo, aA + OFF_ALO + mf * (16 * ROW_STRIDE) + ks * 32);
#pragma unroll
                for (int nf = 0; nf < 4; nf++) {
                    mma_bf16(acc[mf][nf], Ahi, &Bhi[nf >> 1][(nf & 1) * 2]);
                    mma_bf16(acc[mf][nf], Ahi, &Blo[nf >> 1][(nf & 1) * 2]);
                    mma_bf16(acc[mf][nf], Alo, &Bhi[nf >> 1][(nf & 1) * 2]);
                }
            }
        }
    }

    // ---- epilogue: D += bias, write fp32 --------------------------------
    const int row_base = m0 + warp_m * 64 + (lane >> 2);
    const int col_base = n0 + warp_n * 32 + (lane & 3) * 2;
    float bx[4][2];
#pragma unroll
    for (int nf = 0; nf < 4; nf++) {
        bx[nf][0] = bias[col_base + nf * 8];
        bx[nf][1] = bias[col_base + nf * 8 + 1];
    }
#pragma unroll
    for (int mf = 0; mf < 4; mf++) {
        float* p0 = out + (size_t)(row_base + mf * 16) * DOUT + col_base;
        float* p1 = p0 + 8 * DOUT;
#pragma unroll
        for (int nf = 0; nf < 4; nf++) {
            float2 v0, v1;
            v0.x = acc[mf][nf][0] + bx[nf][0];
            v0.y = acc[mf][nf][1] + bx[nf][1];
            v1.x = acc[mf][nf][2] + bx[nf][0];
            v1.y = acc[mf][nf][3] + bx[nf][1];
            *reinterpret_cast<float2*>(p0 + nf * 8) = v0;
            *reinterpret_cast<float2*>(p1 + nf * 8) = v1;
        }
    }
}

// ---------------------------------------------------------------------------
// kernel_launch: prep_x, prep_w, then the GEMM. Graph-capturable; no allocs.
// ---------------------------------------------------------------------------
extern "C" void kernel_launch(void* const* d_in, const int* in_sizes, int n_in,
                              void* d_out, int out_size) {
    const float* x  = (const float*)d_in[0];   // [4,4096,4096]
    const float* W  = (const float*)d_in[1];   // [4096,4096]
    const float* b  = (const float*)d_in[2];   // [4096]
    const float* lA = (const float*)d_in[3];   // [4096,16]
    const float* lB = (const float*)d_in[4];   // [16,4096]
    float* out = (float*)d_out;

    prep_x_kernel<<<(MTOT * (size_t)DIN) / 4 / 256, 256>>>(
        reinterpret_cast<const float4*>(x));
    prep_w_kernel<<<(DOUT * (size_t)DIN) / 256, 256>>>(W, lA, lB);

    cudaFuncSetAttribute(lora_main_kernel,
                         cudaFuncAttributeMaxDynamicSharedMemorySize, SMEM_TOTAL);
    dim3 grid(DOUT / BN, MTOT / BM);   // (32, 64): N fastest for L2 reuse of W
    lora_main_kernel<<<grid, 512, SMEM_TOTAL>>>(b, out);
}

// round 10
// speedup vs baseline: 2.8404x; 2.5466x over previous
#include <cuda_runtime.h>
#include <cuda_fp16.h>
#include <cstdint>
#include <cstddef>

// Problem dims (fixed by the dataset)
#define DIN   4096
#define DOUT  4096
#define MTOT  16384            // B*S = 4*4096
#define LORA_R 16
#define LORA_SCALE 2.0f        // alpha/r = 32/16

// ---------------------------------------------------------------------------
// Scratch: pre-converted fp16 copies (device globals; no allocation)
// ---------------------------------------------------------------------------
__device__ __half g_xh[(size_t)MTOT * DIN];
__device__ __half g_wh[(size_t)DOUT * DIN];

// ---------------------------------------------------------------------------
// Baseline-PTX helpers (no 'a'-suffix features: mma.sync / ldmatrix / cp.async)
// ---------------------------------------------------------------------------
__device__ __forceinline__ uint32_t smem_to_u32(const void* smem_ptr) {
    uint32_t addr;
    asm("{ .reg .u64 tmp; cvta.to.shared.u64 tmp, %1; cvt.u32.u64 %0, tmp; }"
        : "=r"(addr) : "l"(smem_ptr));
    return addr;
}

__device__ __forceinline__ void cp_async16(uint32_t dst, const void* src) {
    asm volatile("cp.async.cg.shared.global [%0], [%1], 16;"
                 :: "r"(dst), "l"(src));
}
__device__ __forceinline__ void cp_commit() {
    asm volatile("cp.async.commit_group;" ::: "memory");
}
template <int N>
__device__ __forceinline__ void cp_wait_group() {
    asm volatile("cp.async.wait_group %0;" :: "n"(N) : "memory");
}

__device__ __forceinline__ void ldsm4(uint32_t* r, uint32_t addr) {
    asm volatile("ldmatrix.sync.aligned.m8n8.x4.shared.b16 {%0,%1,%2,%3}, [%4];"
                 : "=r"(r[0]), "=r"(r[1]), "=r"(r[2]), "=r"(r[3]) : "r"(addr));
}

// D(16x8) += A(16x16,row) * B(8x16 stored [n][k] i.e. col-major KxN), f16->f32
__device__ __forceinline__ void mma_f16(float* c, const uint32_t* a, const uint32_t* b) {
    asm volatile(
        "mma.sync.aligned.m16n8k16.row.col.f32.f16.f16.f32 "
        "{%0,%1,%2,%3}, {%4,%5,%6,%7}, {%8,%9}, {%0,%1,%2,%3};"
        : "+f"(c[0]), "+f"(c[1]), "+f"(c[2]), "+f"(c[3])
        : "r"(a[0]), "r"(a[1]), "r"(a[2]), "r"(a[3]), "r"(b[0]), "r"(b[1]));
}

// ---------------------------------------------------------------------------
// Pre-pass 1: convert x (fp32) to fp16 (round-to-nearest)
// ---------------------------------------------------------------------------
__global__ void prep_x_kernel(const float4* __restrict__ x4) {
    size_t i = (size_t)blockIdx.x * 256 + threadIdx.x;   // 16,777,216 threads
    float4 v = x4[i];
    __half2 p0 = __floats2half2_rn(v.x, v.y);
    __half2 p1 = __floats2half2_rn(v.z, v.w);
    uint2 o;
    o.x = *reinterpret_cast<uint32_t*>(&p0);
    o.y = *reinterpret_cast<uint32_t*>(&p1);
    reinterpret_cast<uint2*>(g_xh)[i] = o;
}

// ---------------------------------------------------------------------------
// Pre-pass 2: W_eff[n,k] = W[n,k] + SCALE * sum_r A[k,r]*B[r,n], to fp16
// ---------------------------------------------------------------------------
__global__ void prep_w_kernel(const float* __restrict__ W,
                              const float* __restrict__ lA,
                              const float* __restrict__ lB) {
    int idx = blockIdx.x * 256 + threadIdx.x;            // 16,777,216 threads
    int n = idx >> 12;
    int k = idx & 4095;
    float acc = W[idx];                                  // W is [DOUT, DIN] row-major
    const float4* a4 = reinterpret_cast<const float4*>(lA + (size_t)k * LORA_R);
#pragma unroll
    for (int r4 = 0; r4 < 4; r4++) {
        float4 a = a4[r4];
        acc = fmaf(LORA_SCALE * a.x, __ldg(lB + (size_t)(r4 * 4 + 0) * DOUT + n), acc);
        acc = fmaf(LORA_SCALE * a.y, __ldg(lB + (size_t)(r4 * 4 + 1) * DOUT + n), acc);
        acc = fmaf(LORA_SCALE * a.z, __ldg(lB + (size_t)(r4 * 4 + 2) * DOUT + n), acc);
        acc = fmaf(LORA_SCALE * a.w, __ldg(lB + (size_t)(r4 * 4 + 3) * DOUT + n), acc);
    }
    g_wh[idx] = __float2half_rn(acc);
}

// ---------------------------------------------------------------------------
// Main GEMM (Ampere-style, baseline PTX only):
//   CTA tile 256(M) x 128(N), BK=32, 4-stage cp.async ring,
//   512 threads / 16 warps as 4(M) x 4(N), warp tile 64x32,
//   single-term fp16 mma, fp32 accumulators.
// SMEM tile rows are 80B-strided (64B data + 16B pad) -> conflict-free LDSM
// (row offsets mod 128B = {0,80,32,112,64,16,96,48}: all 8 slots distinct).
// ---------------------------------------------------------------------------
#define BM          256
#define BN          128
#define BK          32
#define ROW_STRIDE  80                         // 32 fp16 = 64B + 16B pad
#define A_TILE_BYTES (BM * ROW_STRIDE)         // 20480
#define B_TILE_BYTES (BN * ROW_STRIDE)         // 10240
#define OFF_B       A_TILE_BYTES               // 20480
#define STAGE_BYTES (A_TILE_BYTES + B_TILE_BYTES)  // 30720
#define NSTAGE      4
#define SMEM_TOTAL  (NSTAGE * STAGE_BYTES)     // 122880

__global__ void __launch_bounds__(512, 1)
lora_main_kernel(const float* __restrict__ bias, float* __restrict__ out)
{
    extern __shared__ char smem[];
    const uint32_t smem_base = smem_to_u32(smem);
    const int tid    = threadIdx.x;
    const int lane   = tid & 31;
    const int wid    = tid >> 5;
    const int warp_m = wid >> 2;             // 0..3 (64 rows each)
    const int warp_n = wid & 3;              // 0..3 (32 cols each)
    const int n0 = blockIdx.x * BN;          // N tile fastest -> W_eff L2-resident
    const int m0 = blockIdx.y * BM;

    // ---- cp.async slots ---------------------------------------------------
    // A tile: 256 rows x 4 chunks = 1024 chunks -> 2 per thread
    // B tile: 128 rows x 4 chunks =  512 chunks -> 1 per thread
    const int rowA0 = tid >> 2;              // 0..127
    const int cA    = tid & 3;
    const uint32_t soA0 = (uint32_t)(rowA0 * ROW_STRIDE + cA * 16);
    const uint32_t soA1 = soA0 + 128 * ROW_STRIDE;
    const uint32_t soB  = soA0;              // same mapping, 128 rows
    const char* pAh0 = (const char*)g_xh + ((size_t)(m0 + rowA0) * DIN + cA * 8) * 2;
    const size_t rstep = (size_t)128 * DIN * 2;   // +128 rows
    const char* pBh  = (const char*)g_wh + ((size_t)(n0 + rowA0) * DIN + cA * 8) * 2;

    const int NCH = DIN / BK;                // 128 k-chunks

    auto issue_stage = [&](int s) {
        if (s < NCH) {
            const uint32_t sb = smem_base + (uint32_t)(s & (NSTAGE - 1)) * STAGE_BYTES;
            const size_t g = (size_t)s * (BK * 2);   // 64 bytes per k-chunk
            cp_async16(sb + soA0,         pAh0 + g);
            cp_async16(sb + soA1,         pAh0 + g + rstep);
            cp_async16(sb + OFF_B + soB,  pBh + g);
        }
        cp_commit();                         // commit even when empty (group count)
    };

    // ---- ldmatrix address bases (per thread) ----------------------------
    // A (fragment order: row-blocks first, then k-halves):
    //   lanes 0-7->rows0-7@k0-7 | 8-15->rows8-15@k0-7 | 16-23->rows0-7@k8-15 | 24-31->rows8-15@k8-15
    const uint32_t a_off = (uint32_t)((warp_m * 64 + (lane & 15)) * ROW_STRIDE + (lane >> 4) * 16);
    // B (fragment order: k-halves first within an n-block — {b0,b1} =
    //  {B[n,k0-7], B[n,k8-15]} of the SAME n-block):
    const int b_row  = (lane & 7) + ((lane >> 4) << 3);
    const int b_koff = ((lane >> 3) & 1) * 16;
    const uint32_t b_off = (uint32_t)((warp_n * 32 + b_row) * ROW_STRIDE + b_koff);

    float acc[4][4][4];
#pragma unroll
    for (int i = 0; i < 4; i++)
#pragma unroll
        for (int j = 0; j < 4; j++)
#pragma unroll
            for (int e = 0; e < 4; e++) acc[i][j][e] = 0.0f;

    // Prologue: prefetch 3 stages (4-stage ring, up to 3 in flight)
    issue_stage(0); issue_stage(1); issue_stage(2);

    for (int ic = 0; ic < NCH; ++ic) {
        cp_wait_group<2>();                  // stage ic landed (ic+1, ic+2 may fly)
        __syncthreads();                     // all warps done with buf (ic-1)%4
        issue_stage(ic + 3);                 // refill the freed buffer

        const uint32_t sb = smem_base + (uint32_t)(ic & (NSTAGE - 1)) * STAGE_BYTES;
        const uint32_t aA = sb + a_off;
        const uint32_t aB = sb + OFF_B + b_off;
#pragma unroll
        for (int ks = 0; ks < 2; ks++) {
            uint32_t B[2][4];
#pragma unroll
            for (int nb = 0; nb < 2; nb++)
                ldsm4(B[nb], aB + nb * (16 * ROW_STRIDE) + ks * 32);
#pragma unroll
            for (int mf = 0; mf < 4; mf++) {
                uint32_t A[4];
                ldsm4(A, aA + mf * (16 * ROW_STRIDE) + ks * 32);
#pragma unroll
                for (int nf = 0; nf < 4; nf++)
                    mma_f16(acc[mf][nf], A, &B[nf >> 1][(nf & 1) * 2]);
            }
        }
    }

    // ---- epilogue: D += bias, write fp32 --------------------------------
    const int row_base = m0 + warp_m * 64 + (lane >> 2);
    const int col_base = n0 + warp_n * 32 + (lane & 3) * 2;
    float bx[4][2];
#pragma unroll
    for (int nf = 0; nf < 4; nf++) {
        bx[nf][0] = bias[col_base + nf * 8];
        bx[nf][1] = bias[col_base + nf * 8 + 1];
    }
#pragma unroll
    for (int mf = 0; mf < 4; mf++) {
        float* p0 = out + (size_t)(row_base + mf * 16) * DOUT + col_base;
        float* p1 = p0 + 8 * DOUT;
#pragma unroll
        for (int nf = 0; nf < 4; nf++) {
            float2 v0, v1;
            v0.x = acc[mf][nf][0] + bx[nf][0];
            v0.y = acc[mf][nf][1] + bx[nf][1];
            v1.x = acc[mf][nf][2] + bx[nf][0];
            v1.y = acc[mf][nf][3] + bx[nf][1];
            *reinterpret_cast<float2*>(p0 + nf * 8) = v0;
            *reinterpret_cast<float2*>(p1 + nf * 8) = v1;
        }
    }
}

// ---------------------------------------------------------------------------
// kernel_launch: prep_x, prep_w, then the GEMM. Graph-capturable; no allocs.
// ---------------------------------------------------------------------------
extern "C" void kernel_launch(void* const* d_in, const int* in_sizes, int n_in,
                              void* d_out, int out_size) {
    const float* x  = (const float*)d_in[0];   // [4,4096,4096]
    const float* W  = (const float*)d_in[1];   // [4096,4096]
    const float* b  = (const float*)d_in[2];   // [4096]
    const float* lA = (const float*)d_in[3];   // [4096,16]
    const float* lB = (const float*)d_in[4];   // [16,4096]
    float* out = (float*)d_out;

    prep_x_kernel<<<(MTOT * (size_t)DIN) / 4 / 256, 256>>>(
        reinterpret_cast<const float4*>(x));
    prep_w_kernel<<<(DOUT * (size_t)DIN) / 256, 256>>>(W, lA, lB);

    cudaFuncSetAttribute(lora_main_kernel,
                         cudaFuncAttributeMaxDynamicSharedMemorySize, SMEM_TOTAL);
    dim3 grid(DOUT / BN, MTOT / BM);   // (32, 64): N fastest for L2 reuse of W
    lora_main_kernel<<<grid, 512, SMEM_TOTAL>>>(b, out);
}